// round 10
// baseline (speedup 1.0000x reference)
#include <cuda_runtime.h>
#include <cuda_fp16.h>
#include <cstdint>

// SubLSTM: T=512, B=64, I=H=1024, L=2, gates (i,o,z), fixed forget fg=sigmoid(f)
//   gates = sigmoid(x W^T + h R^T + bi + bh)
//   c' = c*fg + z - i ;  h' = sigmoid(c') - o
// Output: [out (T*B*H)][h0_fin][h1_fin][c0_fin][c1_fin]

#define T_STEPS 512
#define BATCH   64
#define HSZ     1024
#define G3      3072
#define TBH     (T_STEPS * BATCH * HSZ)
#define BH      (BATCH * HSZ)
#define NB      128
#define HSLOTH  (HSZ * BATCH)        // 65536 halves per h slot

// Device-global scratch (allocation-free rule)
__device__ float  g_gx[(size_t)T_STEPS * BATCH * G3];   // [t][3072][64]
__device__ float  g_h0[(size_t)T_STEPS * BATCH * HSZ];  // [t][b][h] layer-0 out
// h rotation (3 slots), fp16, A-FRAGMENT order for m16n8k16:
//   half idx = kb*1024 + (b>>4)*256 + lane*8 + (hi*4 + hb8*2 + lo)
__device__ __half g_htrh[3 * HSLOTH];
__device__ unsigned g_arrive;                 // legacy atomic barrier (init only)
__device__ unsigned g_gen;
__device__ unsigned g_wflag[NB * 32];         // producer: h of steps [0,w) written
__device__ unsigned g_rflag[NB * 32];         // reader: finished reads of steps [0,r)

__device__ __forceinline__ float sigf(float x) { return 1.f / (1.f + __expf(-x)); }

// ===================== PTX helpers =====================
__device__ __forceinline__ uint32_t smem_u32(const void* p) {
    uint32_t a;
    asm("{ .reg .u64 t; cvta.to.shared.u64 t, %1; cvt.u32.u64 %0, t; }" : "=r"(a) : "l"(p));
    return a;
}
#define CP_ASYNC16(dst, src) \
    asm volatile("cp.async.ca.shared.global [%0], [%1], 16;" :: "r"(dst), "l"(src) : "memory")
#define CP_ASYNC_CG16(dst, src) \
    asm volatile("cp.async.cg.shared.global [%0], [%1], 16;" :: "r"(dst), "l"(src) : "memory")
#define CP_COMMIT() asm volatile("cp.async.commit_group;" ::: "memory")
#define CPWAIT(n)   asm volatile("cp.async.wait_group %0;" :: "n"(n) : "memory")

__device__ __forceinline__ unsigned ld_acq(const unsigned* p) {
    unsigned v;
    asm volatile("ld.acquire.gpu.u32 %0, [%1];" : "=r"(v) : "l"(p) : "memory");
    return v;
}
__device__ __forceinline__ void st_rel(unsigned* p, unsigned v) {
    asm volatile("st.release.gpu.u32 [%0], %1;" :: "l"(p), "r"(v) : "memory");
}

__device__ __forceinline__ uint32_t f2tf32(float x) {
    uint32_t u;
    asm("cvt.rna.tf32.f32 %0, %1;" : "=r"(u) : "f"(x));
    return u;
}
__device__ __forceinline__ void mma_tf32(float& d0, float& d1, float& d2, float& d3,
                                         uint32_t a0, uint32_t a1, uint32_t a2, uint32_t a3,
                                         uint32_t b0, uint32_t b1) {
    asm volatile("mma.sync.aligned.m16n8k8.row.col.f32.tf32.tf32.f32 "
                 "{%0,%1,%2,%3}, {%4,%5,%6,%7}, {%8,%9}, {%0,%1,%2,%3};"
                 : "+f"(d0), "+f"(d1), "+f"(d2), "+f"(d3)
                 : "r"(a0), "r"(a1), "r"(a2), "r"(a3), "r"(b0), "r"(b1));
}
__device__ __forceinline__ void mma_f16(float& d0, float& d1, float& d2, float& d3,
                                        uint32_t a0, uint32_t a1, uint32_t a2, uint32_t a3,
                                        uint32_t b0, uint32_t b1) {
    asm volatile("mma.sync.aligned.m16n8k16.row.col.f32.f16.f16.f32 "
                 "{%0,%1,%2,%3}, {%4,%5,%6,%7}, {%8,%9}, {%0,%1,%2,%3};"
                 : "+f"(d0), "+f"(d1), "+f"(d2), "+f"(d3)
                 : "r"(a0), "r"(a1), "r"(a2), "r"(a3), "r"(b0), "r"(b1));
}

// Legacy generation barrier (atomic). Used ONCE per launch to fence init.
__device__ __forceinline__ void grid_sync_atomic() {
    __threadfence();
    __syncthreads();
    if (threadIdx.x == 0) {
        unsigned gen = *(volatile unsigned*)&g_gen;
        unsigned t = atomicInc(&g_arrive, NB - 1);
        if (t == NB - 1) {
            __threadfence();
            *(volatile unsigned*)&g_gen = gen + 1;
        } else {
            while (*(volatile unsigned*)&g_gen == gen) { }
        }
        __threadfence();
    }
    __syncthreads();
}

// ---------------------------------------------------------------------------
// TF32 mma.sync GEMM (unchanged, passing)
// ---------------------------------------------------------------------------
#define SMPAD 36
__global__ __launch_bounds__(256, 2) void gemm_tf32_kernel(
    const float* __restrict__ A, const float* __restrict__ W,
    const float* __restrict__ bi, const float* __restrict__ bh,
    float* __restrict__ C)
{
    __shared__ float smA[128 * SMPAD];
    __shared__ float smB[128 * SMPAD];

    const int tid = threadIdx.x;
    const int wid = tid >> 5;
    const int lane = tid & 31;
    const int g   = lane >> 2;
    const int tig = lane & 3;
    const int wm  = wid & 3;
    const int wn  = wid >> 2;
    const int m0  = blockIdx.y * 128;
    const int n0  = blockIdx.x * 128;

    const uint32_t sa = smem_u32(smA);
    const uint32_t sb = smem_u32(smB);

    float acc[2][8][4];
#pragma unroll
    for (int mt = 0; mt < 2; mt++)
#pragma unroll
        for (int nt = 0; nt < 8; nt++)
#pragma unroll
            for (int r = 0; r < 4; r++) acc[mt][nt][r] = 0.f;

    const int lrow = tid >> 3;
    const int lq   = tid & 7;

#pragma unroll 1
    for (int kt = 0; kt < HSZ / 32; kt++) {
        const int k0 = kt * 32;
#pragma unroll
        for (int i = 0; i < 4; i++) {
            const int row = lrow + i * 32;
            CP_ASYNC16(sa + (uint32_t)(row * SMPAD + lq * 4) * 4,
                       A + (size_t)(m0 + row) * HSZ + k0 + lq * 4);
            CP_ASYNC16(sb + (uint32_t)(row * SMPAD + lq * 4) * 4,
                       W + (size_t)(n0 + row) * HSZ + k0 + lq * 4);
        }
        CP_COMMIT();
        CPWAIT(0);
        __syncthreads();

#pragma unroll
        for (int s = 0; s < 4; s++) {
            const int kc = s * 8 + tig;
            uint32_t af[2][4];
#pragma unroll
            for (int mt = 0; mt < 2; mt++) {
                const int r0 = (wm * 32 + mt * 16 + g) * SMPAD;
                af[mt][0] = f2tf32(smA[r0 + kc]);
                af[mt][1] = f2tf32(smA[r0 + 8 * SMPAD + kc]);
                af[mt][2] = f2tf32(smA[r0 + kc + 4]);
                af[mt][3] = f2tf32(smA[r0 + 8 * SMPAD + kc + 4]);
            }
#pragma unroll
            for (int nt = 0; nt < 8; nt++) {
                const int nr = (wn * 64 + nt * 8 + g) * SMPAD;
                uint32_t b0 = f2tf32(smB[nr + kc]);
                uint32_t b1 = f2tf32(smB[nr + kc + 4]);
#pragma unroll
                for (int mt = 0; mt < 2; mt++)
                    mma_tf32(acc[mt][nt][0], acc[mt][nt][1], acc[mt][nt][2], acc[mt][nt][3],
                             af[mt][0], af[mt][1], af[mt][2], af[mt][3], b0, b1);
            }
        }
        __syncthreads();
    }

    float* stage = smA;
    const int m_lane = tid & 63;
    const int n_off  = tid >> 6;
#pragma unroll 1
    for (int ci = 0; ci < 4; ci++) {
        if (wn == (ci >> 1)) {
            const int ntb = (ci & 1) * 4;
#pragma unroll
            for (int mt = 0; mt < 2; mt++) {
                const int r0 = wm * 32 + mt * 16 + g;
#pragma unroll
                for (int nn = 0; nn < 4; nn++) {
                    const int nt = ntb + nn;
                    const int nl = nn * 8 + 2 * tig;
                    stage[r0 * 33 + nl]           = acc[mt][nt][0];
                    stage[r0 * 33 + nl + 1]       = acc[mt][nt][1];
                    stage[(r0 + 8) * 33 + nl]     = acc[mt][nt][2];
                    stage[(r0 + 8) * 33 + nl + 1] = acc[mt][nt][3];
                }
            }
        }
        __syncthreads();
#pragma unroll
        for (int p = 0; p < 8; p++) {
            const int nlc = p * 4 + n_off;
            const int ng  = n0 + ci * 32 + nlc;
            const float bias = __ldg(bi + ng) + __ldg(bh + ng);
#pragma unroll
            for (int half = 0; half < 2; half++) {
                const int m  = m_lane + half * 64;
                const int mg = m0 + m;
                C[((size_t)(mg >> 6) * G3 + ng) * BATCH + (mg & 63)] =
                    stage[m * 33 + nlc] + bias;
            }
        }
        __syncthreads();
    }
}

// ---------------------------------------------------------------------------
// Persistent fp16 MMA recurrence, producer/consumer dataflow (no full barrier).
// 128 CTAs x 128 threads. h chunk c (cols 128c..128c+127) produced by CTAs
// 16c..16c+15 -> consumers poll wflag of just those before cp.async'ing it.
// 3 h slots (mod-3) + rflag guard the WAR overwrite.
// Smem: R 48KB (B-frag order) + 3 x 16KB A bufs = 96KB. Cell in registers.
// ---------------------------------------------------------------------------
__global__ __launch_bounds__(128) void recurrent_kernel(
    const float* __restrict__ gx,   // [T][3072][64]
    const float* __restrict__ R,    // [3072][1024]
    const float* __restrict__ f,    // [1024]
    float* __restrict__ hb,         // [T][B][H]
    float* __restrict__ hfin,       // [B][H]
    float* __restrict__ cfin)       // [B][H]
{
    extern __shared__ __align__(16) char s_dyn[];
    __half* Rsh = (__half*)s_dyn;            // 49152 B
    char*   Asm = s_dyn + 49152;             // 3 bufs x 16384 B

    const int tid  = threadIdx.x;
    const int wm   = tid >> 5;
    const int lane = tid & 31;
    const int g    = lane >> 2;
    const int tig  = lane & 3;
    const int bid  = blockIdx.x;
    const int colbase = bid * 8;

    // Reset flags (replay safety); fenced by grid_sync_atomic below.
    if (tid == 0) { g_wflag[bid * 32] = 0; g_rflag[bid * 32] = 0; }

    // ---- Load R slice -> B-fragment-order fp16 smem, once ----
    for (int v = tid; v < 6144; v += 128) {
        const int n  = v >> 8;
        const int k  = (v & 255) * 4;
        const int nt = n >> 3, nloc = n & 7;
        const int row = nt * HSZ + colbase + nloc;
        float4 w = *(const float4*)(R + (size_t)row * HSZ + k);
        const int kb = k >> 4, kin = k & 15;
        const int t0 = (kin & 7) >> 1;
        const int hi = kin >> 3;
        __half* base = Rsh + (((kb * 3 + nt) * 32 + nloc * 4) * 4 + hi * 2);
        *(__half2*)(base + (t0    ) * 4) = __floats2half2_rn(w.x, w.y);
        *(__half2*)(base + (t0 + 1) * 4) = __floats2half2_rn(w.z, w.w);
    }

    grid_sync_atomic();   // flag resets + R smem visible/done everywhere

    const int r0 = wm * 16 + g;
    const int r1 = r0 + 8;
    const int c0g = colbase + 2 * tig;
    const int c1g = c0g + 1;
    const float fg0 = sigf(__ldg(f + c0g));
    const float fg1 = sigf(__ldg(f + c1g));
    float cs00 = 0.f, cs01 = 0.f, cs10 = 0.f, cs11 = 0.f;

    const uint32_t hsA = smem_u32(Asm);
    const uint32_t a_lm = hsA + (uint32_t)(wm * 512 + lane * 16);
    const int wp = (colbase >> 4) * 1024 + wm * 256 + lane * 8
                 + ((colbase >> 3) & 1) * 4;
    const unsigned* mywf = g_wflag + ((tid & 15) * 32);  // reused with chunk offset
    const unsigned* myrf = g_rflag + ((tid & 127) * 32);

    // Copy one 16KB chunk (8 k16-blocks), pure linear: 8 cp.async per thread
#define ISSUE(cidx, buf) do {                                                   \
        const char* s_ = (const char*)hsrc + (size_t)(cidx) * 16384 + tid * 16; \
        uint32_t d_ = hsA + (uint32_t)(buf) * 16384 + (uint32_t)(tid * 16);     \
        _Pragma("unroll")                                                       \
        for (int j_ = 0; j_ < 8; j_++)                                          \
            CP_ASYNC_CG16(d_ + j_ * 2048, s_ + j_ * 2048);                      \
        CP_COMMIT();                                                            \
    } while (0)
    // Wait for the 16 producers of chunk ch to have written h of step t-1
#define WAITW(ch) while (ld_acq(g_wflag + (((ch) * 16 + (tid & 15)) * 32)) < (unsigned)t) { }

#pragma unroll 1
    for (int t = 0; t < T_STEPS; t++) {
        const int sw = t % 3;            // h slot to write
        const int sr = (t + 2) % 3;      // h slot to read (= (t-1)%3)

        // gx preactivations (12 scalars, early issue)
        const float* gxt = gx + (size_t)t * G3 * BATCH;
        const float xi00 = __ldcg(gxt + (size_t)c0g * BATCH + r0);
        const float xi01 = __ldcg(gxt + (size_t)c1g * BATCH + r0);
        const float xi10 = __ldcg(gxt + (size_t)c0g * BATCH + r1);
        const float xi11 = __ldcg(gxt + (size_t)c1g * BATCH + r1);
        const float xo00 = __ldcg(gxt + (size_t)(HSZ + c0g) * BATCH + r0);
        const float xo01 = __ldcg(gxt + (size_t)(HSZ + c1g) * BATCH + r0);
        const float xo10 = __ldcg(gxt + (size_t)(HSZ + c0g) * BATCH + r1);
        const float xo11 = __ldcg(gxt + (size_t)(HSZ + c1g) * BATCH + r1);
        const float xz00 = __ldcg(gxt + (size_t)(2 * HSZ + c0g) * BATCH + r0);
        const float xz01 = __ldcg(gxt + (size_t)(2 * HSZ + c1g) * BATCH + r0);
        const float xz10 = __ldcg(gxt + (size_t)(2 * HSZ + c0g) * BATCH + r1);
        const float xz11 = __ldcg(gxt + (size_t)(2 * HSZ + c1g) * BATCH + r1);

        float a[3][4] = {{0.f,0.f,0.f,0.f},{0.f,0.f,0.f,0.f},{0.f,0.f,0.f,0.f}};

        if (t > 0) {
            const __half* hsrc = g_htrh + (size_t)sr * HSLOTH;
            WAITW(0);
            WAITW(1);
            __syncthreads();             // all producer-acquires visible CTA-wide
            ISSUE(0, 0);
            ISSUE(1, 1);
#pragma unroll 1
            for (int c = 0; c < 8; c++) {
                if (c == 7) CPWAIT(0); else CPWAIT(1);
                if (c < 6) WAITW(c + 2);
                __syncthreads();         // chunk c visible; buf (c+2)%3 free
                if (c < 6) ISSUE(c + 2, (c + 2) % 3);
                const uint32_t a_ch = a_lm + (uint32_t)(c % 3) * 16384;
#pragma unroll
                for (int blk = 0; blk < 8; blk++) {
                    uint4 Af;
                    asm volatile("ld.shared.v4.b32 {%0,%1,%2,%3}, [%4];"
                                 : "=r"(Af.x), "=r"(Af.y), "=r"(Af.z), "=r"(Af.w)
                                 : "r"(a_ch + (uint32_t)(blk * 2048)));
                    const int kbg = c * 8 + blk;
                    const uint2* bf = (const uint2*)((const char*)Rsh
                                      + (size_t)(kbg * 3) * 256 + lane * 8);
#pragma unroll
                    for (int nt = 0; nt < 3; nt++) {
                        const uint2 Bf = bf[nt * 32];
                        mma_f16(a[nt][0], a[nt][1], a[nt][2], a[nt][3],
                                Af.x, Af.y, Af.z, Af.w, Bf.x, Bf.y);
                    }
                }
            }
        }

        // Publish: finished all global h reads for this step.
        if (tid == 0) st_rel(&g_rflag[bid * 32], (unsigned)(t + 1));

        // WAR guard: before overwriting slot sw (last written at t-3, read at
        // step t-2), ensure every CTA finished step t-2 reads (rflag >= t-1).
        if (t >= 3) {
            while (ld_acq(myrf) < (unsigned)(t - 1)) { }
            __syncthreads();
        }

        // ---- epilogue: gates, cell, hidden ----
        const float i00 = sigf(a[0][0] + xi00), i01 = sigf(a[0][1] + xi01);
        const float i10 = sigf(a[0][2] + xi10), i11 = sigf(a[0][3] + xi11);
        const float o00 = sigf(a[1][0] + xo00), o01 = sigf(a[1][1] + xo01);
        const float o10 = sigf(a[1][2] + xo10), o11 = sigf(a[1][3] + xo11);
        const float z00 = sigf(a[2][0] + xz00), z01 = sigf(a[2][1] + xz01);
        const float z10 = sigf(a[2][2] + xz10), z11 = sigf(a[2][3] + xz11);

        cs00 = cs00 * fg0 + z00 - i00;
        cs01 = cs01 * fg1 + z01 - i01;
        cs10 = cs10 * fg0 + z10 - i10;
        cs11 = cs11 * fg1 + z11 - i11;
        const float h00 = sigf(cs00) - o00;
        const float h01 = sigf(cs01) - o01;
        const float h10 = sigf(cs10) - o10;
        const float h11 = sigf(cs11) - o11;

        // h -> fp16 A-fragment slot: 4 contiguous halves, one 8B store
        {
            __half2 p0 = __floats2half2_rn(h00, h01);
            __half2 p1 = __floats2half2_rn(h10, h11);
            uint2 pk;
            pk.x = *(unsigned*)&p0;
            pk.y = *(unsigned*)&p1;
            __half* slot = g_htrh + (size_t)sw * HSLOTH + wp;
            __stcg((uint2*)slot, pk);
        }

        // h -> sequence output [t][b][h] (full precision)
        float* hbt = hb + (size_t)t * BH;
        __stcg((float2*)(hbt + (size_t)r0 * HSZ + c0g), make_float2(h00, h01));
        __stcg((float2*)(hbt + (size_t)r1 * HSZ + c0g), make_float2(h10, h11));

        if (t == T_STEPS - 1) {
            *(float2*)(hfin + (size_t)r0 * HSZ + c0g) = make_float2(h00, h01);
            *(float2*)(hfin + (size_t)r1 * HSZ + c0g) = make_float2(h10, h11);
            *(float2*)(cfin + (size_t)r0 * HSZ + c0g) = make_float2(cs00, cs01);
            *(float2*)(cfin + (size_t)r1 * HSZ + c0g) = make_float2(cs10, cs11);
        } else {
            __syncthreads();             // all h stores done CTA-wide
            if (tid == 0) st_rel(&g_wflag[bid * 32], (unsigned)(t + 1));
        }
    }
#undef ISSUE
#undef WAITW
}

// ---------------------------------------------------------------------------
extern "C" void kernel_launch(void* const* d_in, const int* in_sizes, int n_in,
                              void* d_out, int out_size)
{
    const float* x   = (const float*)d_in[0];
    const float* W0  = (const float*)d_in[1];
    const float* R0  = (const float*)d_in[2];
    const float* bi0 = (const float*)d_in[3];
    const float* bh0 = (const float*)d_in[4];
    const float* f0  = (const float*)d_in[5];
    const float* W1  = (const float*)d_in[6];
    const float* R1  = (const float*)d_in[7];
    const float* bi1 = (const float*)d_in[8];
    const float* bh1 = (const float*)d_in[9];
    const float* f1  = (const float*)d_in[10];
    float* out = (float*)d_out;

    float *gx, *h0;
    cudaGetSymbolAddress((void**)&gx, g_gx);
    cudaGetSymbolAddress((void**)&h0, g_h0);

    const int RSMEM = 49152 + 3 * 16384;   // 98304 B
    cudaFuncSetAttribute(recurrent_kernel,
                         cudaFuncAttributeMaxDynamicSharedMemorySize, RSMEM);

    dim3 ggrid(G3 / 128, (T_STEPS * BATCH) / 128);   // (24, 256)

    // Layer 0
    gemm_tf32_kernel<<<ggrid, 256>>>(x, W0, bi0, bh0, gx);
    recurrent_kernel<<<NB, 128, RSMEM>>>(gx, R0, f0, h0,
                                         out + TBH,              // h0 final
                                         out + TBH + 2 * BH);    // c0 final
    // Layer 1
    gemm_tf32_kernel<<<ggrid, 256>>>(h0, W1, bi1, bh1, gx);
    recurrent_kernel<<<NB, 128, RSMEM>>>(gx, R1, f1, out,
                                         out + TBH + BH,         // h1 final
                                         out + TBH + 3 * BH);    // c1 final
}

// round 11
// speedup vs baseline: 1.3107x; 1.3107x over previous
#include <cuda_runtime.h>
#include <cuda_fp16.h>
#include <cstdint>

// SubLSTM: T=512, B=64, I=H=1024, L=2, gates (i,o,z), fixed forget fg=sigmoid(f)
//   gates = sigmoid(x W^T + h R^T + bi + bh)
//   c' = c*fg + z - i ;  h' = sigmoid(c') - o
// Output: [out (T*B*H)][h0_fin][h1_fin][c0_fin][c1_fin]

#define T_STEPS 512
#define BATCH   64
#define HSZ     1024
#define G3      3072
#define TBH     (T_STEPS * BATCH * HSZ)
#define BH      (BATCH * HSZ)
#define NB      128
#define HSLOTH  (HSZ * BATCH)        // 65536 halves per h slot

// Device-global scratch (allocation-free rule)
__device__ float  g_gx[(size_t)T_STEPS * BATCH * G3];   // [t][3072][64]
__device__ float  g_h0[(size_t)T_STEPS * BATCH * HSZ];  // [t][b][h] layer-0 out
// h ping-pong (2 slots), fp16, A-FRAGMENT order for m16n8k16:
//   half idx = kb*1024 + (b>>4)*256 + lane*8 + (hi*4 + hb8*2 + lo)
__device__ __half g_htrh[2 * HSLOTH];
__device__ unsigned g_arrive;                 // legacy atomic barrier (init only)
__device__ unsigned g_gen;
__device__ volatile unsigned g_flags[NB * 32]; // per-CTA step flags, 128B stride

__device__ __forceinline__ float sigf(float x) { return 1.f / (1.f + __expf(-x)); }

// ===================== PTX helpers =====================
__device__ __forceinline__ uint32_t smem_u32(const void* p) {
    uint32_t a;
    asm("{ .reg .u64 t; cvta.to.shared.u64 t, %1; cvt.u32.u64 %0, t; }" : "=r"(a) : "l"(p));
    return a;
}
#define CP_ASYNC16(dst, src) \
    asm volatile("cp.async.ca.shared.global [%0], [%1], 16;" :: "r"(dst), "l"(src) : "memory")
#define CP_ASYNC_CG16(dst, src) \
    asm volatile("cp.async.cg.shared.global [%0], [%1], 16;" :: "r"(dst), "l"(src) : "memory")
#define CP_COMMIT() asm volatile("cp.async.commit_group;" ::: "memory")
#define CPWAIT(n)   asm volatile("cp.async.wait_group %0;" :: "n"(n) : "memory")

__device__ __forceinline__ uint32_t f2tf32(float x) {
    uint32_t u;
    asm("cvt.rna.tf32.f32 %0, %1;" : "=r"(u) : "f"(x));
    return u;
}
__device__ __forceinline__ void mma_tf32(float& d0, float& d1, float& d2, float& d3,
                                         uint32_t a0, uint32_t a1, uint32_t a2, uint32_t a3,
                                         uint32_t b0, uint32_t b1) {
    asm volatile("mma.sync.aligned.m16n8k8.row.col.f32.tf32.tf32.f32 "
                 "{%0,%1,%2,%3}, {%4,%5,%6,%7}, {%8,%9}, {%0,%1,%2,%3};"
                 : "+f"(d0), "+f"(d1), "+f"(d2), "+f"(d3)
                 : "r"(a0), "r"(a1), "r"(a2), "r"(a3), "r"(b0), "r"(b1));
}
__device__ __forceinline__ void mma_f16(float& d0, float& d1, float& d2, float& d3,
                                        uint32_t a0, uint32_t a1, uint32_t a2, uint32_t a3,
                                        uint32_t b0, uint32_t b1) {
    asm volatile("mma.sync.aligned.m16n8k16.row.col.f32.f16.f16.f32 "
                 "{%0,%1,%2,%3}, {%4,%5,%6,%7}, {%8,%9}, {%0,%1,%2,%3};"
                 : "+f"(d0), "+f"(d1), "+f"(d2), "+f"(d3)
                 : "r"(a0), "r"(a1), "r"(a2), "r"(a3), "r"(b0), "r"(b1));
}

// Legacy generation barrier (atomic). Used ONCE per launch to fence init.
__device__ __forceinline__ void grid_sync_atomic() {
    __threadfence();
    __syncthreads();
    if (threadIdx.x == 0) {
        unsigned gen = *(volatile unsigned*)&g_gen;
        unsigned t = atomicInc(&g_arrive, NB - 1);
        if (t == NB - 1) {
            __threadfence();
            *(volatile unsigned*)&g_gen = gen + 1;
        } else {
            while (*(volatile unsigned*)&g_gen == gen) { }
        }
        __threadfence();
    }
    __syncthreads();
}

// Per-step flag barrier: each CTA writes its own flag (distinct L2 lines),
// thread i polls CTA i's flag. Requires blockDim.x >= NB.
__device__ __forceinline__ void flag_barrier(unsigned val) {
    __threadfence();
    __syncthreads();
    if (threadIdx.x == 0) g_flags[blockIdx.x * 32] = val;
    if (threadIdx.x < NB) {
        while (g_flags[threadIdx.x * 32] < val) { }
    }
    __threadfence();
    __syncthreads();
}

// ---------------------------------------------------------------------------
// TF32 mma.sync GEMM (unchanged, passing)
// ---------------------------------------------------------------------------
#define SMPAD 36
__global__ __launch_bounds__(256, 2) void gemm_tf32_kernel(
    const float* __restrict__ A, const float* __restrict__ W,
    const float* __restrict__ bi, const float* __restrict__ bh,
    float* __restrict__ C)
{
    __shared__ float smA[128 * SMPAD];
    __shared__ float smB[128 * SMPAD];

    const int tid = threadIdx.x;
    const int wid = tid >> 5;
    const int lane = tid & 31;
    const int g   = lane >> 2;
    const int tig = lane & 3;
    const int wm  = wid & 3;
    const int wn  = wid >> 2;
    const int m0  = blockIdx.y * 128;
    const int n0  = blockIdx.x * 128;

    const uint32_t sa = smem_u32(smA);
    const uint32_t sb = smem_u32(smB);

    float acc[2][8][4];
#pragma unroll
    for (int mt = 0; mt < 2; mt++)
#pragma unroll
        for (int nt = 0; nt < 8; nt++)
#pragma unroll
            for (int r = 0; r < 4; r++) acc[mt][nt][r] = 0.f;

    const int lrow = tid >> 3;
    const int lq   = tid & 7;

#pragma unroll 1
    for (int kt = 0; kt < HSZ / 32; kt++) {
        const int k0 = kt * 32;
#pragma unroll
        for (int i = 0; i < 4; i++) {
            const int row = lrow + i * 32;
            CP_ASYNC16(sa + (uint32_t)(row * SMPAD + lq * 4) * 4,
                       A + (size_t)(m0 + row) * HSZ + k0 + lq * 4);
            CP_ASYNC16(sb + (uint32_t)(row * SMPAD + lq * 4) * 4,
                       W + (size_t)(n0 + row) * HSZ + k0 + lq * 4);
        }
        CP_COMMIT();
        CPWAIT(0);
        __syncthreads();

#pragma unroll
        for (int s = 0; s < 4; s++) {
            const int kc = s * 8 + tig;
            uint32_t af[2][4];
#pragma unroll
            for (int mt = 0; mt < 2; mt++) {
                const int r0 = (wm * 32 + mt * 16 + g) * SMPAD;
                af[mt][0] = f2tf32(smA[r0 + kc]);
                af[mt][1] = f2tf32(smA[r0 + 8 * SMPAD + kc]);
                af[mt][2] = f2tf32(smA[r0 + kc + 4]);
                af[mt][3] = f2tf32(smA[r0 + 8 * SMPAD + kc + 4]);
            }
#pragma unroll
            for (int nt = 0; nt < 8; nt++) {
                const int nr = (wn * 64 + nt * 8 + g) * SMPAD;
                uint32_t b0 = f2tf32(smB[nr + kc]);
                uint32_t b1 = f2tf32(smB[nr + kc + 4]);
#pragma unroll
                for (int mt = 0; mt < 2; mt++)
                    mma_tf32(acc[mt][nt][0], acc[mt][nt][1], acc[mt][nt][2], acc[mt][nt][3],
                             af[mt][0], af[mt][1], af[mt][2], af[mt][3], b0, b1);
            }
        }
        __syncthreads();
    }

    float* stage = smA;
    const int m_lane = tid & 63;
    const int n_off  = tid >> 6;
#pragma unroll 1
    for (int ci = 0; ci < 4; ci++) {
        if (wn == (ci >> 1)) {
            const int ntb = (ci & 1) * 4;
#pragma unroll
            for (int mt = 0; mt < 2; mt++) {
                const int r0 = wm * 32 + mt * 16 + g;
#pragma unroll
                for (int nn = 0; nn < 4; nn++) {
                    const int nt = ntb + nn;
                    const int nl = nn * 8 + 2 * tig;
                    stage[r0 * 33 + nl]           = acc[mt][nt][0];
                    stage[r0 * 33 + nl + 1]       = acc[mt][nt][1];
                    stage[(r0 + 8) * 33 + nl]     = acc[mt][nt][2];
                    stage[(r0 + 8) * 33 + nl + 1] = acc[mt][nt][3];
                }
            }
        }
        __syncthreads();
#pragma unroll
        for (int p = 0; p < 8; p++) {
            const int nlc = p * 4 + n_off;
            const int ng  = n0 + ci * 32 + nlc;
            const float bias = __ldg(bi + ng) + __ldg(bh + ng);
#pragma unroll
            for (int half = 0; half < 2; half++) {
                const int m  = m_lane + half * 64;
                const int mg = m0 + m;
                C[((size_t)(mg >> 6) * G3 + ng) * BATCH + (mg & 63)] =
                    stage[m * 33 + nlc] + bias;
            }
        }
        __syncthreads();
    }
}

// ---------------------------------------------------------------------------
// Persistent fp16 MMA recurrence: 128 CTAs x 256 threads = 2 warp-groups.
// Group g owns K-chunks 4g..4g+3 with its OWN cp.async pipeline (3 private
// 16KB bufs, named barrier grp+1). Separate fp32 accumulators, reduced once
// per step via smem scratch. Epilogue/h-stores by group 0 (identical to the
// round-9 passing layout). flag_barrier between steps.
// Smem: R 48KB + 6 x 16KB A bufs + 6KB scratch = 150KB.
// ---------------------------------------------------------------------------
__global__ __launch_bounds__(256) void recurrent_kernel(
    const float* __restrict__ gx,   // [T][3072][64]
    const float* __restrict__ R,    // [3072][1024]
    const float* __restrict__ f,    // [1024]
    float* __restrict__ hb,         // [T][B][H]
    float* __restrict__ hfin,       // [B][H]
    float* __restrict__ cfin)       // [B][H]
{
    extern __shared__ __align__(16) char s_dyn[];
    __half* Rsh = (__half*)s_dyn;               // 49152 B
    char*   Asm = s_dyn + 49152;                // 6 bufs x 16384 B
    float*  red = (float*)(s_dyn + 49152 + 98304);  // 6144 B scratch

    const int tid  = threadIdx.x;
    const int wid  = tid >> 5;
    const int grp  = wid >> 2;          // warp-group 0/1
    const int wm   = wid & 3;
    const int gtid = tid & 127;
    const int lane = tid & 31;
    const int g    = lane >> 2;
    const int tig  = lane & 3;
    const int bid  = blockIdx.x;
    const int colbase = bid * 8;
    const int gb   = grp * 4;           // first global chunk of this group

    // Reset this CTA's step flag (replay safety); fenced by grid_sync_atomic.
    if (tid == 0) g_flags[bid * 32] = 0;

    // ---- Load R slice -> B-fragment-order fp16 smem, once ----
    for (int v = tid; v < 6144; v += 256) {
        const int n  = v >> 8;
        const int k  = (v & 255) * 4;
        const int nt = n >> 3, nloc = n & 7;
        const int row = nt * HSZ + colbase + nloc;
        float4 w = *(const float4*)(R + (size_t)row * HSZ + k);
        const int kb = k >> 4, kin = k & 15;
        const int t0 = (kin & 7) >> 1;
        const int hi = kin >> 3;
        __half* base = Rsh + (((kb * 3 + nt) * 32 + nloc * 4) * 4 + hi * 2);
        *(__half2*)(base + (t0    ) * 4) = __floats2half2_rn(w.x, w.y);
        *(__half2*)(base + (t0 + 1) * 4) = __floats2half2_rn(w.z, w.w);
    }

    grid_sync_atomic();   // flag resets + R smem visible/done

    const int r0 = wm * 16 + g;
    const int r1 = r0 + 8;
    const int c0g = colbase + 2 * tig;
    const int c1g = c0g + 1;
    const float fg0 = sigf(__ldg(f + c0g));
    const float fg1 = sigf(__ldg(f + c1g));
    float cs00 = 0.f, cs01 = 0.f, cs10 = 0.f, cs11 = 0.f;

    const uint32_t hsA  = smem_u32(Asm);
    const uint32_t grpb = (uint32_t)grp * 3 * 16384;
    const uint32_t a_lm = hsA + grpb + (uint32_t)(wm * 512 + lane * 16);
    const int wp = (colbase >> 4) * 1024 + wm * 256 + lane * 8
                 + ((colbase >> 3) & 1) * 4;

#define BARG() asm volatile("bar.sync %0, 128;" :: "r"(grp + 1) : "memory")
    // Copy one 16KB chunk (8 k16-blocks), pure linear: 8 cp.async per thread
#define ISSUE(cglob, buf) do {                                                   \
        const char* s_ = (const char*)hsrc + (size_t)(cglob) * 16384 + gtid * 16; \
        uint32_t d_ = hsA + grpb + (uint32_t)(buf) * 16384 + (uint32_t)(gtid * 16); \
        _Pragma("unroll")                                                        \
        for (int j_ = 0; j_ < 8; j_++)                                           \
            CP_ASYNC_CG16(d_ + j_ * 2048, s_ + j_ * 2048);                       \
        CP_COMMIT();                                                             \
    } while (0)

#pragma unroll 1
    for (int t = 0; t < T_STEPS; t++) {
        // gx preactivations (group 0 only; early issue)
        float xi00 = 0.f, xi01 = 0.f, xi10 = 0.f, xi11 = 0.f;
        float xo00 = 0.f, xo01 = 0.f, xo10 = 0.f, xo11 = 0.f;
        float xz00 = 0.f, xz01 = 0.f, xz10 = 0.f, xz11 = 0.f;
        if (grp == 0) {
            const float* gxt = gx + (size_t)t * G3 * BATCH;
            xi00 = __ldcg(gxt + (size_t)c0g * BATCH + r0);
            xi01 = __ldcg(gxt + (size_t)c1g * BATCH + r0);
            xi10 = __ldcg(gxt + (size_t)c0g * BATCH + r1);
            xi11 = __ldcg(gxt + (size_t)c1g * BATCH + r1);
            xo00 = __ldcg(gxt + (size_t)(HSZ + c0g) * BATCH + r0);
            xo01 = __ldcg(gxt + (size_t)(HSZ + c1g) * BATCH + r0);
            xo10 = __ldcg(gxt + (size_t)(HSZ + c0g) * BATCH + r1);
            xo11 = __ldcg(gxt + (size_t)(HSZ + c1g) * BATCH + r1);
            xz00 = __ldcg(gxt + (size_t)(2 * HSZ + c0g) * BATCH + r0);
            xz01 = __ldcg(gxt + (size_t)(2 * HSZ + c1g) * BATCH + r0);
            xz10 = __ldcg(gxt + (size_t)(2 * HSZ + c0g) * BATCH + r1);
            xz11 = __ldcg(gxt + (size_t)(2 * HSZ + c1g) * BATCH + r1);
        }

        float a[3][4] = {{0.f,0.f,0.f,0.f},{0.f,0.f,0.f,0.f},{0.f,0.f,0.f,0.f}};

        if (t > 0) {
            const __half* hsrc = g_htrh + (size_t)((t - 1) & 1) * HSLOTH;
            ISSUE(gb + 0, 0);
            ISSUE(gb + 1, 1);
#pragma unroll 1
            for (int l = 0; l < 4; l++) {
                if (l == 3) CPWAIT(0); else CPWAIT(1);
                BARG();                  // chunk l visible; buf (l+2)%3 free
                if (l < 2) ISSUE(gb + l + 2, (l + 2) % 3);
                const uint32_t a_ch = a_lm + (uint32_t)(l % 3) * 16384;
#pragma unroll
                for (int blk = 0; blk < 8; blk++) {
                    uint4 Af;
                    asm volatile("ld.shared.v4.b32 {%0,%1,%2,%3}, [%4];"
                                 : "=r"(Af.x), "=r"(Af.y), "=r"(Af.z), "=r"(Af.w)
                                 : "r"(a_ch + (uint32_t)(blk * 2048)));
                    const int kbg = (gb + l) * 8 + blk;
                    const uint2* bf = (const uint2*)((const char*)Rsh
                                      + (size_t)(kbg * 3) * 256 + lane * 8);
#pragma unroll
                    for (int nt = 0; nt < 3; nt++) {
                        const uint2 Bf = bf[nt * 32];
                        mma_f16(a[nt][0], a[nt][1], a[nt][2], a[nt][3],
                                Af.x, Af.y, Af.z, Af.w, Bf.x, Bf.y);
                    }
                }
            }
            // ---- reduce group-1 partials into group-0 accumulators ----
            __syncthreads();
            if (grp == 1) {
                float* d = red + gtid * 12;
#pragma unroll
                for (int nt = 0; nt < 3; nt++)
#pragma unroll
                    for (int r = 0; r < 4; r++) d[nt * 4 + r] = a[nt][r];
            }
            __syncthreads();
            if (grp == 0) {
                const float* s = red + gtid * 12;
#pragma unroll
                for (int nt = 0; nt < 3; nt++)
#pragma unroll
                    for (int r = 0; r < 4; r++) a[nt][r] += s[nt * 4 + r];
            }
        }

        // ---- epilogue (group 0 only): gates, cell, hidden ----
        if (grp == 0) {
            const float i00 = sigf(a[0][0] + xi00), i01 = sigf(a[0][1] + xi01);
            const float i10 = sigf(a[0][2] + xi10), i11 = sigf(a[0][3] + xi11);
            const float o00 = sigf(a[1][0] + xo00), o01 = sigf(a[1][1] + xo01);
            const float o10 = sigf(a[1][2] + xo10), o11 = sigf(a[1][3] + xo11);
            const float z00 = sigf(a[2][0] + xz00), z01 = sigf(a[2][1] + xz01);
            const float z10 = sigf(a[2][2] + xz10), z11 = sigf(a[2][3] + xz11);

            cs00 = cs00 * fg0 + z00 - i00;
            cs01 = cs01 * fg1 + z01 - i01;
            cs10 = cs10 * fg0 + z10 - i10;
            cs11 = cs11 * fg1 + z11 - i11;
            const float h00 = sigf(cs00) - o00;
            const float h01 = sigf(cs01) - o01;
            const float h10 = sigf(cs10) - o10;
            const float h11 = sigf(cs11) - o11;

            // h -> fp16 A-fragment ping-pong: 4 contiguous halves, one 8B store
            {
                __half2 p0 = __floats2half2_rn(h00, h01);
                __half2 p1 = __floats2half2_rn(h10, h11);
                uint2 pk;
                pk.x = *(unsigned*)&p0;
                pk.y = *(unsigned*)&p1;
                __half* slot = g_htrh + (size_t)(t & 1) * HSLOTH + wp;
                __stcg((uint2*)slot, pk);
            }

            // h -> sequence output [t][b][h] (full precision)
            float* hbt = hb + (size_t)t * BH;
            __stcg((float2*)(hbt + (size_t)r0 * HSZ + c0g), make_float2(h00, h01));
            __stcg((float2*)(hbt + (size_t)r1 * HSZ + c0g), make_float2(h10, h11));

            if (t == T_STEPS - 1) {
                *(float2*)(hfin + (size_t)r0 * HSZ + c0g) = make_float2(h00, h01);
                *(float2*)(hfin + (size_t)r1 * HSZ + c0g) = make_float2(h10, h11);
                *(float2*)(cfin + (size_t)r0 * HSZ + c0g) = make_float2(cs00, cs01);
                *(float2*)(cfin + (size_t)r1 * HSZ + c0g) = make_float2(cs10, cs11);
            }
        }

        if (t < T_STEPS - 1) flag_barrier((unsigned)(t + 1));
    }
#undef ISSUE
#undef BARG
}

// ---------------------------------------------------------------------------
extern "C" void kernel_launch(void* const* d_in, const int* in_sizes, int n_in,
                              void* d_out, int out_size)
{
    const float* x   = (const float*)d_in[0];
    const float* W0  = (const float*)d_in[1];
    const float* R0  = (const float*)d_in[2];
    const float* bi0 = (const float*)d_in[3];
    const float* bh0 = (const float*)d_in[4];
    const float* f0  = (const float*)d_in[5];
    const float* W1  = (const float*)d_in[6];
    const float* R1  = (const float*)d_in[7];
    const float* bi1 = (const float*)d_in[8];
    const float* bh1 = (const float*)d_in[9];
    const float* f1  = (const float*)d_in[10];
    float* out = (float*)d_out;

    float *gx, *h0;
    cudaGetSymbolAddress((void**)&gx, g_gx);
    cudaGetSymbolAddress((void**)&h0, g_h0);

    const int RSMEM = 49152 + 6 * 16384 + 6144;   // 153600 B
    cudaFuncSetAttribute(recurrent_kernel,
                         cudaFuncAttributeMaxDynamicSharedMemorySize, RSMEM);

    dim3 ggrid(G3 / 128, (T_STEPS * BATCH) / 128);   // (24, 256)

    // Layer 0
    gemm_tf32_kernel<<<ggrid, 256>>>(x, W0, bi0, bh0, gx);
    recurrent_kernel<<<NB, 256, RSMEM>>>(gx, R0, f0, h0,
                                         out + TBH,              // h0 final
                                         out + TBH + 2 * BH);    // c0 final
    // Layer 1
    gemm_tf32_kernel<<<ggrid, 256>>>(h0, W1, bi1, bh1, gx);
    recurrent_kernel<<<NB, 256, RSMEM>>>(gx, R1, f1, out,
                                         out + TBH + BH,         // h1 final
                                         out + TBH + 3 * BH);    // c1 final
}